// round 11
// baseline (speedup 1.0000x reference)
#include <cuda_runtime.h>
#include <cuda_bf16.h>
#include <cuda_fp16.h>
#include <cstdint>

#define NN 50000
#define EE 250000
#define HH 4
#define CC 64
#define DNODE 256
#define EDD 194
#define KPAD 256
#define NOUT 256
#define KEDGE 224

// ---------------- scratch (device globals; no runtime allocation) ----------------
__device__ float  g_q   [(size_t)NN * DNODE];
__device__ float  g_k   [(size_t)NN * DNODE];
__device__ float  g_v   [(size_t)NN * DNODE];
__device__ float  g_skip[(size_t)NN * DNODE];
__device__ __half g_eh  [(size_t)EE * DNODE];     // edge embeddings, fp16, dst-sorted

// edge sort-by-dst (once per call; edge_index identical for both layers)
__device__ int g_cnt [NN];
__device__ int g_off [NN + 1];
__device__ int g_pos [NN];
__device__ int g_order[EE];
__device__ int g_srcs [EE];    // src gathered into sorted order

// split-bf16 operand buffers (edge operands stored in dst-sorted order)
__device__ __nv_bfloat16 g_ahi[(size_t)NN * KPAD];
__device__ __nv_bfloat16 g_alo[(size_t)NN * KPAD];
__device__ __nv_bfloat16 g_ehi[(size_t)EE * KPAD];
__device__ __nv_bfloat16 g_elo[(size_t)EE * KPAD];
// per layer: [Wq|Wk|Wv|Ws] (4*256 rows) then We (256 rows); 2 layers
__device__ __nv_bfloat16 g_whi[10][(size_t)NOUT * KPAD];
__device__ __nv_bfloat16 g_wlo[10][(size_t)NOUT * KPAD];
__device__ float g_bias[2][4 * NOUT];

// ==================== merged split-bf16 HMMA GEMM (node + edge in one grid) ====================
#define BM 128
#define BN 128
#define BK 32
#define NTHR 512
#define NSTAGE 3
#define LDS_A 40
#define TSZ (BM * LDS_A)
#define STAGE_ELEMS (4 * TSZ)
#define GEMM_SMEM (NSTAGE * STAGE_ELEMS * 2)

#define NODE_TX 391          // (NN+127)/128
#define EDGE_TX 1954         // (EE+127)/128
#define NODE_CTAS (NODE_TX * 8)
#define TOTAL_CTAS (NODE_CTAS + EDGE_TX * 2)

__device__ __forceinline__ uint32_t smem_u32(const void* p) {
    uint32_t a;
    asm("{ .reg .u64 t; cvta.to.shared.u64 t, %1; cvt.u32.u64 %0, t; }" : "=r"(a) : "l"(p));
    return a;
}
__device__ __forceinline__ void cpa16(uint32_t dst, const void* src, int szbytes) {
    asm volatile("cp.async.ca.shared.global [%0], [%1], 16, %2;"
                 :: "r"(dst), "l"(src), "r"(szbytes));
}
#define CP_COMMIT() asm volatile("cp.async.commit_group;" ::: "memory")
#define CP_WAIT(n)  asm volatile("cp.async.wait_group %0;" :: "n"(n) : "memory")

__device__ __forceinline__ void ldsm4(uint32_t* r, uint32_t a) {
    asm volatile("ldmatrix.sync.aligned.m8n8.x4.shared.b16 {%0,%1,%2,%3}, [%4];"
                 : "=r"(r[0]), "=r"(r[1]), "=r"(r[2]), "=r"(r[3]) : "r"(a));
}
__device__ __forceinline__ void mma_bf16(float* c, const uint32_t* a, const uint32_t* b) {
    asm volatile(
        "mma.sync.aligned.m16n8k16.row.col.f32.bf16.bf16.f32 "
        "{%0,%1,%2,%3}, {%4,%5,%6,%7}, {%8,%9}, {%0,%1,%2,%3};"
        : "+f"(c[0]), "+f"(c[1]), "+f"(c[2]), "+f"(c[3])
        : "r"(a[0]), "r"(a[1]), "r"(a[2]), "r"(a[3]), "r"(b[0]), "r"(b[1]));
}

__global__ __launch_bounds__(NTHR) void gemm_layer(
    const __nv_bfloat16* __restrict__ nAhi, const __nv_bfloat16* __restrict__ nAlo,
    const __nv_bfloat16* __restrict__ eAhi, const __nv_bfloat16* __restrict__ eAlo,
    const __nv_bfloat16* __restrict__ Whi,  const __nv_bfloat16* __restrict__ Wlo,
    const float* __restrict__ bias,
    float* __restrict__ q, float* __restrict__ kk,
    float* __restrict__ vv, float* __restrict__ skip,
    __half* __restrict__ eh)
{
    extern __shared__ __nv_bfloat16 smem[];

    const int tid  = threadIdx.x;
    const int wid  = tid >> 5;
    const int lane = tid & 31;

    // decode part
    const int bx = blockIdx.x;
    const bool is_node = bx < NODE_CTAS;
    int gx, gy;
    if (is_node) { gx = bx % NODE_TX; gy = bx / NODE_TX; }
    else         { int j = bx - NODE_CTAS; gx = j % EDGE_TX; gy = j / EDGE_TX; }

    const int m0 = gx * BM;
    const int M_ = is_node ? NN : EE;
    const int K_ = is_node ? KPAD : KEDGE;
    const __nv_bfloat16* Ahi = is_node ? nAhi : eAhi;
    const __nv_bfloat16* Alo = is_node ? nAlo : eAlo;
    const size_t wbase = is_node ? 0 : (size_t)(4 * NOUT) * KPAD;
    const int nglob0 = gy * BN;

    const int wm = (wid & 3) * 32;
    const int wn = (wid >> 2) * 32;
    const int gr  = lane >> 2;
    const int tig = lane & 3;

    const int r0  = tid >> 2;
    const int cg0 = (tid & 3) * 8;
    const int gmA = m0 + r0;
    const int aok = (gmA < M_) ? 16 : 0;
    const size_t arow = (size_t)(aok ? gmA : 0) * KPAD;
    const size_t brow = wbase + (size_t)(nglob0 + r0) * KPAD;

    const int nk = K_ / BK;

    float acc[2][4][4];
#pragma unroll
    for (int i = 0; i < 2; i++)
#pragma unroll
        for (int j = 0; j < 4; j++)
#pragma unroll
            for (int r = 0; r < 4; r++) acc[i][j][r] = 0.f;

    uint32_t sbase = smem_u32(smem);

    auto load_stage = [&](int st, int kc) {
        uint32_t b = sbase + (uint32_t)(st * STAGE_ELEMS) * 2;
        uint32_t d = b + (uint32_t)(r0 * LDS_A + cg0) * 2;
        cpa16(d,                    Ahi + arow + kc + cg0, aok);
        cpa16(d + (uint32_t)TSZ*2,  Alo + arow + kc + cg0, aok);
        cpa16(d + (uint32_t)TSZ*4,  Whi + brow + kc + cg0, 16);
        cpa16(d + (uint32_t)TSZ*6,  Wlo + brow + kc + cg0, 16);
        CP_COMMIT();
    };

    const int aRow = lane & 15;
    const int aCol = (lane >> 4) * 8;
    const uint32_t aOff = (uint32_t)((wm + aRow) * LDS_A + aCol) * 2;
    const int bRow = wn + (lane & 7) + ((lane >> 4) << 3);
    const int bCol = ((lane >> 3) & 1) * 8;
    const uint32_t bOff = (uint32_t)(bRow * LDS_A + bCol) * 2;

    load_stage(0, 0);
    if (nk > 1) load_stage(1, BK);

    for (int ki = 0; ki < nk; ki++) {
        if (ki + 2 < nk) {
            load_stage((ki + 2) % NSTAGE, (ki + 2) * BK);
            CP_WAIT(2);
        } else if (ki + 1 < nk) {
            CP_WAIT(1);
        } else {
            CP_WAIT(0);
        }
        __syncthreads();

        uint32_t stb = sbase + (uint32_t)((ki % NSTAGE) * STAGE_ELEMS) * 2;
        uint32_t aHiB = stb, aLoB = stb + TSZ * 2;
        uint32_t bHiB = stb + TSZ * 4, bLoB = stb + TSZ * 6;

#pragma unroll
        for (int ks = 0; ks < BK; ks += 16) {
            uint32_t ah[2][4], al[2][4];
#pragma unroll
            for (int mt = 0; mt < 2; mt++) {
                uint32_t o = aOff + (uint32_t)(mt * 16 * LDS_A + ks) * 2;
                ldsm4(ah[mt], aHiB + o);
                ldsm4(al[mt], aLoB + o);
            }
            uint32_t bhf[8], blf[8];
#pragma unroll
            for (int p = 0; p < 2; p++) {
                uint32_t o = bOff + (uint32_t)(p * 16 * LDS_A + ks) * 2;
                ldsm4(bhf + 4 * p, bHiB + o);
                ldsm4(blf + 4 * p, bLoB + o);
            }
#pragma unroll
            for (int mt = 0; mt < 2; mt++)
#pragma unroll
                for (int nt = 0; nt < 4; nt++) {
                    mma_bf16(acc[mt][nt], ah[mt], bhf + nt * 2);
                    mma_bf16(acc[mt][nt], ah[mt], blf + nt * 2);
                    mma_bf16(acc[mt][nt], al[mt], bhf + nt * 2);
                }
        }
        __syncthreads();
    }

    // ---- epilogue ----
    if (is_node) {
        const int ob = gy >> 1;
        float* C = (ob == 0) ? q : (ob == 1) ? kk : (ob == 2) ? vv : skip;
        const int n0l = (gy & 1) * BN;
#pragma unroll
        for (int nt = 0; nt < 4; nt++) {
            int lc = wn + nt * 8 + tig * 2;
            float2 b2 = *(const float2*)(bias + nglob0 + lc);
            int gc = n0l + lc;
#pragma unroll
            for (int mt = 0; mt < 2; mt++) {
                int gm = m0 + wm + mt * 16 + gr;
                if (gm < M_) {
                    float2 v0 = make_float2(acc[mt][nt][0] + b2.x, acc[mt][nt][1] + b2.y);
                    *(float2*)(C + (size_t)gm * NOUT + gc) = v0;
                }
                if (gm + 8 < M_) {
                    float2 v1 = make_float2(acc[mt][nt][2] + b2.x, acc[mt][nt][3] + b2.y);
                    *(float2*)(C + (size_t)(gm + 8) * NOUT + gc) = v1;
                }
            }
        }
    } else {
#pragma unroll
        for (int nt = 0; nt < 4; nt++) {
            int gc = nglob0 + wn + nt * 8 + tig * 2;
#pragma unroll
            for (int mt = 0; mt < 2; mt++) {
                int gm = m0 + wm + mt * 16 + gr;
                if (gm < M_) {
                    __half2 h0 = __floats2half2_rn(acc[mt][nt][0], acc[mt][nt][1]);
                    *(__half2*)(eh + (size_t)gm * NOUT + gc) = h0;
                }
                if (gm + 8 < M_) {
                    __half2 h1 = __floats2half2_rn(acc[mt][nt][2], acc[mt][nt][3]);
                    *(__half2*)(eh + (size_t)(gm + 8) * NOUT + gc) = h1;
                }
            }
        }
    }
}

// ==================== conversion kernels ====================
__global__ void split_feat(const float* __restrict__ X,
                           __nv_bfloat16* __restrict__ hi, __nv_bfloat16* __restrict__ lo,
                           int M, int Kin)
{
    int idx = blockIdx.x * blockDim.x + threadIdx.x;
    if (idx >= M * KPAD) return;
    int k = idx & (KPAD - 1);
    float v = 0.f;
    if (k < Kin) v = X[(size_t)(idx >> 8) * Kin + k];
    __nv_bfloat16 h = __float2bfloat16(v);
    hi[idx] = h;
    lo[idx] = __float2bfloat16(v - __bfloat162float(h));
}

// edge features, gathered into dst-sorted order; only k < KEDGE written
__global__ void split_feat_edge(const float* __restrict__ ea, const int* __restrict__ order,
                                __nv_bfloat16* __restrict__ hi, __nv_bfloat16* __restrict__ lo)
{
    int idx = blockIdx.x * blockDim.x + threadIdx.x;
    if (idx >= EE * KPAD) return;
    int k = idx & (KPAD - 1);
    if (k >= KEDGE) return;
    int i = idx >> 8;
    int eo = order[i];
    float v = (k < EDD) ? ea[(size_t)eo * EDD + k] : 0.f;
    __nv_bfloat16 h = __float2bfloat16(v);
    hi[idx] = h;
    lo[idx] = __float2bfloat16(v - __bfloat162float(h));
}

__global__ void split_weight(const float* __restrict__ W,
                             __nv_bfloat16* __restrict__ hi, __nv_bfloat16* __restrict__ lo,
                             int Kin)
{
    int idx = blockIdx.x * blockDim.x + threadIdx.x;
    if (idx >= NOUT * KPAD) return;
    int n = idx & 255, k = idx >> 8;
    float v = (k < Kin) ? W[(size_t)k * NOUT + n] : 0.f;
    __nv_bfloat16 h = __float2bfloat16(v);
    hi[(size_t)n * KPAD + k] = h;
    lo[(size_t)n * KPAD + k] = __float2bfloat16(v - __bfloat162float(h));
}

__global__ void pack_bias(const float* __restrict__ bq, const float* __restrict__ bk,
                          const float* __restrict__ bv, const float* __restrict__ bs,
                          float* __restrict__ out)
{
    int i = blockIdx.x * blockDim.x + threadIdx.x;
    if (i >= 4 * NOUT) return;
    const float* src = (i < 256) ? bq : (i < 512) ? bk : (i < 768) ? bv : bs;
    out[i] = src[i & 255];
}

// ==================== edge sort-by-dst (once per call) ====================
__global__ void zero_cnt(int* __restrict__ cnt) {
    int i = blockIdx.x * blockDim.x + threadIdx.x;
    if (i < NN) cnt[i] = 0;
}
__global__ void hist_dst(const int* __restrict__ dst, int* __restrict__ cnt) {
    int i = blockIdx.x * blockDim.x + threadIdx.x;
    if (i < EE) atomicAdd(&cnt[dst[i]], 1);
}
__global__ __launch_bounds__(1024) void scan_cnt(const int* __restrict__ cnt,
                                                 int* __restrict__ off, int* __restrict__ pos)
{
    __shared__ int ssum[1024];
    const int tid = threadIdx.x;
    const int PER = (NN + 1023) / 1024;
    const int base = tid * PER;
    int s = 0;
    for (int j = 0; j < PER; j++) {
        int i = base + j;
        if (i < NN) s += cnt[i];
    }
    ssum[tid] = s;
    __syncthreads();
    for (int d = 1; d < 1024; d <<= 1) {
        int t = (tid >= d) ? ssum[tid - d] : 0;
        __syncthreads();
        ssum[tid] += t;
        __syncthreads();
    }
    int run = (tid > 0) ? ssum[tid - 1] : 0;
    for (int j = 0; j < PER; j++) {
        int i = base + j;
        if (i < NN) {
            off[i] = run;
            pos[i] = run;
            run += cnt[i];
        }
    }
    if (tid == 1023) off[NN] = run;
}
__global__ void scatter_edges(const int* __restrict__ dst, const int* __restrict__ src,
                              int* __restrict__ pos, int* __restrict__ order,
                              int* __restrict__ srcs)
{
    int i = blockIdx.x * blockDim.x + threadIdx.x;
    if (i >= EE) return;
    int p = atomicAdd(&pos[dst[i]], 1);
    order[p] = i;
    srcs[p] = src[i];
}

// ==================== fused per-dst attention ====================
// one warp per dst node; e rows are dst-sorted fp16, read sequentially.
__global__ __launch_bounds__(256) void edge_dst(
    const float* __restrict__ q, const float* __restrict__ k,
    const __half* __restrict__ eemb, const float* __restrict__ v,
    const int* __restrict__ srcs, const int* __restrict__ off,
    const float* __restrict__ skip,
    float* __restrict__ outf,
    __nv_bfloat16* __restrict__ hi, __nv_bfloat16* __restrict__ lo,
    int mode)
{
    int w = (blockIdx.x * blockDim.x + threadIdx.x) >> 5;
    if (w >= NN) return;
    const int lane = threadIdx.x & 31;
    const int h = lane >> 3;
    const int part = lane & 7;
    const int co = h * CC + part * 8;

    const int start = off[w], end = off[w + 1];

    const float4* qp = (const float4*)(q + (size_t)w * DNODE + co);
    float4 q0 = qp[0], q1 = qp[1];

    float acc[8] = {0.f, 0.f, 0.f, 0.f, 0.f, 0.f, 0.f, 0.f};
    float den = 0.f;

    for (int i = start; i < end; i++) {
        int s = srcs[i];
        const float4* kp = (const float4*)(k + (size_t)s * DNODE + co);
        float4 k0 = kp[0], k1 = kp[1];

        // fp16 e row: 8 halves = 16B per lane
        uint4 eu = *(const uint4*)(eemb + (size_t)i * DNODE + co);
        const __half2* hp = (const __half2*)&eu;
        float2 ea = __half22float2(hp[0]);
        float2 eb = __half22float2(hp[1]);
        float2 ec = __half22float2(hp[2]);
        float2 ed = __half22float2(hp[3]);
        float4 e0 = make_float4(ea.x, ea.y, eb.x, eb.y);
        float4 e1 = make_float4(ec.x, ec.y, ed.x, ed.y);

        float dot = q0.x * (k0.x + e0.x) + q0.y * (k0.y + e0.y)
                  + q0.z * (k0.z + e0.z) + q0.w * (k0.w + e0.w)
                  + q1.x * (k1.x + e1.x) + q1.y * (k1.y + e1.y)
                  + q1.z * (k1.z + e1.z) + q1.w * (k1.w + e1.w);
        dot += __shfl_xor_sync(0xffffffffu, dot, 1);
        dot += __shfl_xor_sync(0xffffffffu, dot, 2);
        dot += __shfl_xor_sync(0xffffffffu, dot, 4);

        float ex = __expf(dot * 0.125f);
        den += ex;

        const float4* vp = (const float4*)(v + (size_t)s * DNODE + co);
        float4 v0 = vp[0], v1 = vp[1];
        acc[0] += ex * (v0.x + e0.x); acc[1] += ex * (v0.y + e0.y);
        acc[2] += ex * (v0.z + e0.z); acc[3] += ex * (v0.w + e0.w);
        acc[4] += ex * (v1.x + e1.x); acc[5] += ex * (v1.y + e1.y);
        acc[6] += ex * (v1.z + e1.z); acc[7] += ex * (v1.w + e1.w);
    }

    float inv = 1.0f / (den + 1e-16f);
    const float4* sp = (const float4*)(skip + (size_t)w * DNODE + co);
    float4 s0 = sp[0], s1 = sp[1];
    float r[8];
    r[0] = acc[0] * inv + s0.x; r[1] = acc[1] * inv + s0.y;
    r[2] = acc[2] * inv + s0.z; r[3] = acc[3] * inv + s0.w;
    r[4] = acc[4] * inv + s1.x; r[5] = acc[5] * inv + s1.y;
    r[6] = acc[6] * inv + s1.z; r[7] = acc[7] * inv + s1.w;

    if (mode == 1) {
        ushort4 hv[2], lv[2];
#pragma unroll
        for (int g = 0; g < 2; g++) {
#pragma unroll
            for (int j = 0; j < 4; j++) {
                float x = fmaxf(r[g * 4 + j], 0.f);
                __nv_bfloat16 hb = __float2bfloat16(x);
                __nv_bfloat16 lb = __float2bfloat16(x - __bfloat162float(hb));
                ((unsigned short*)&hv[g])[j] = *(unsigned short*)&hb;
                ((unsigned short*)&lv[g])[j] = *(unsigned short*)&lb;
            }
        }
        size_t base = (size_t)w * KPAD + co;
        *(ushort4*)(hi + base)     = hv[0];
        *(ushort4*)(lo + base)     = lv[0];
        *(ushort4*)(hi + base + 4) = hv[1];
        *(ushort4*)(lo + base + 4) = lv[1];
    } else {
        float4* op = (float4*)(outf + (size_t)w * DNODE + co);
        op[0] = make_float4(r[0], r[1], r[2], r[3]);
        op[1] = make_float4(r[4], r[5], r[6], r[7]);
    }
}

// ==================== host side ====================
extern "C" void kernel_launch(void* const* d_in, const int* in_sizes, int n_in,
                              void* d_out, int out_size)
{
    const float* x   = (const float*)d_in[0];
    const int*   ei  = (const int*)  d_in[1];
    const float* ea  = (const float*)d_in[2];
    // per layer, weight buffer order: Wq, Wk, Wv, Ws, We
    const float* W1[5] = { (const float*)d_in[3],  (const float*)d_in[5],
                           (const float*)d_in[7],  (const float*)d_in[10],
                           (const float*)d_in[9] };
    const float* W2[5] = { (const float*)d_in[12], (const float*)d_in[14],
                           (const float*)d_in[16], (const float*)d_in[19],
                           (const float*)d_in[18] };
    const int Kin[5] = { DNODE, DNODE, DNODE, DNODE, EDD };

    const int* src = ei;
    const int* dst = ei + EE;
    float* out = (float*)d_out;

    float *q, *k, *v, *skip, *bias;
    __half* eh;
    int *cnt, *off, *pos, *order, *srcs;
    __nv_bfloat16 *ahi, *alo, *ehi, *elo, *whi, *wlo;
    cudaGetSymbolAddress((void**)&q,     g_q);
    cudaGetSymbolAddress((void**)&k,     g_k);
    cudaGetSymbolAddress((void**)&v,     g_v);
    cudaGetSymbolAddress((void**)&skip,  g_skip);
    cudaGetSymbolAddress((void**)&eh,    g_eh);
    cudaGetSymbolAddress((void**)&cnt,   g_cnt);
    cudaGetSymbolAddress((void**)&off,   g_off);
    cudaGetSymbolAddress((void**)&pos,   g_pos);
    cudaGetSymbolAddress((void**)&order, g_order);
    cudaGetSymbolAddress((void**)&srcs,  g_srcs);
    cudaGetSymbolAddress((void**)&ahi,   g_ahi);
    cudaGetSymbolAddress((void**)&alo,   g_alo);
    cudaGetSymbolAddress((void**)&ehi,   g_ehi);
    cudaGetSymbolAddress((void**)&elo,   g_elo);
    cudaGetSymbolAddress((void**)&whi,   g_whi);
    cudaGetSymbolAddress((void**)&wlo,   g_wlo);
    cudaGetSymbolAddress((void**)&bias,  g_bias);
    const size_t WS = (size_t)NOUT * KPAD;

    cudaFuncSetAttribute(gemm_layer, cudaFuncAttributeMaxDynamicSharedMemorySize, GEMM_SMEM);

    // ---- edge sort by dst (once; shared by both layers) ----
    zero_cnt<<<(NN + 255) / 256, 256>>>(cnt);
    hist_dst<<<(EE + 255) / 256, 256>>>(dst, cnt);
    scan_cnt<<<1, 1024>>>(cnt, off, pos);
    scatter_edges<<<(EE + 255) / 256, 256>>>(dst, src, pos, order, srcs);

    // ---- conversions ----
    for (int i = 0; i < 5; i++) {
        split_weight<<<(NOUT * KPAD + 255) / 256, 256>>>(W1[i], whi + i * WS,       wlo + i * WS,       Kin[i]);
        split_weight<<<(NOUT * KPAD + 255) / 256, 256>>>(W2[i], whi + (5 + i) * WS, wlo + (5 + i) * WS, Kin[i]);
    }
    pack_bias<<<4, 256>>>((const float*)d_in[4],  (const float*)d_in[6],
                          (const float*)d_in[8],  (const float*)d_in[11], bias);
    pack_bias<<<4, 256>>>((const float*)d_in[13], (const float*)d_in[15],
                          (const float*)d_in[17], (const float*)d_in[20], bias + 4 * NOUT);

    split_feat_edge<<<((size_t)EE * KPAD + 255) / 256, 256>>>(ea, order, ehi, elo);
    split_feat<<<((size_t)NN * KPAD + 255) / 256, 256>>>(x, ahi, alo, NN, DNODE);

    // ---- layer 1 ----
    gemm_layer<<<TOTAL_CTAS, NTHR, GEMM_SMEM>>>(ahi, alo, ehi, elo,
                                                whi, wlo, bias,
                                                q, k, v, skip, eh);
    edge_dst<<<(NN * 32 + 255) / 256, 256>>>(q, k, eh, v, srcs, off, skip,
                                             nullptr, ahi, alo, 1);

    // ---- layer 2 ----
    gemm_layer<<<TOTAL_CTAS, NTHR, GEMM_SMEM>>>(ahi, alo, ehi, elo,
                                                whi + 5 * WS, wlo + 5 * WS, bias + 4 * NOUT,
                                                q, k, v, skip, eh);
    edge_dst<<<(NN * 32 + 255) / 256, 256>>>(q, k, eh, v, srcs, off, skip,
                                             out, nullptr, nullptr, 0);
}

// round 12
// speedup vs baseline: 1.0482x; 1.0482x over previous
#include <cuda_runtime.h>
#include <cuda_bf16.h>
#include <cuda_fp16.h>
#include <cstdint>

#define NN 50000
#define EE 250000
#define HH 4
#define CC 64
#define DNODE 256
#define EDD 194
#define KPAD 256
#define NOUT 256
#define KEDGE 224

// ---------------- scratch (device globals; no runtime allocation) ----------------
__device__ float  g_q   [(size_t)NN * DNODE];
__device__ float  g_k   [(size_t)NN * DNODE];
__device__ float  g_v   [(size_t)NN * DNODE];
__device__ float  g_skip[(size_t)NN * DNODE];
__device__ __half g_eh  [(size_t)EE * DNODE];   // edge embeddings, fp16, ORIGINAL edge order

// edge sort-by-dst (once per call; edge_index identical for both layers)
__device__ int g_cnt [NN];
__device__ int g_off [NN + 1];
__device__ int g_pos [NN];
__device__ int g_order[EE];
__device__ int g_srcs [EE];   // src gathered into sorted order

// split-bf16 operand buffers
__device__ __nv_bfloat16 g_ahi[(size_t)NN * KPAD];
__device__ __nv_bfloat16 g_alo[(size_t)NN * KPAD];
__device__ __nv_bfloat16 g_ehi[(size_t)EE * KPAD];
__device__ __nv_bfloat16 g_elo[(size_t)EE * KPAD];
// per layer: [Wq|Wk|Wv|Ws] (4*256 rows) then We (256 rows); 2 layers
__device__ __nv_bfloat16 g_whi[10][(size_t)NOUT * KPAD];
__device__ __nv_bfloat16 g_wlo[10][(size_t)NOUT * KPAD];
__device__ float g_bias[2][4 * NOUT];

// ==================== split-bf16 HMMA GEMM (R8-validated core) ====================
#define BM 128
#define BN 128
#define BK 32
#define NTHR 512
#define NSTAGE 3
#define LDS_A 40
#define TSZ (BM * LDS_A)
#define STAGE_ELEMS (4 * TSZ)
#define GEMM_SMEM (NSTAGE * STAGE_ELEMS * 2)

__device__ __forceinline__ uint32_t smem_u32(const void* p) {
    uint32_t a;
    asm("{ .reg .u64 t; cvta.to.shared.u64 t, %1; cvt.u32.u64 %0, t; }" : "=r"(a) : "l"(p));
    return a;
}
__device__ __forceinline__ void cpa16(uint32_t dst, const void* src, int szbytes) {
    asm volatile("cp.async.ca.shared.global [%0], [%1], 16, %2;"
                 :: "r"(dst), "l"(src), "r"(szbytes));
}
#define CP_COMMIT() asm volatile("cp.async.commit_group;" ::: "memory")
#define CP_WAIT(n)  asm volatile("cp.async.wait_group %0;" :: "n"(n) : "memory")

__device__ __forceinline__ void ldsm4(uint32_t* r, uint32_t a) {
    asm volatile("ldmatrix.sync.aligned.m8n8.x4.shared.b16 {%0,%1,%2,%3}, [%4];"
                 : "=r"(r[0]), "=r"(r[1]), "=r"(r[2]), "=r"(r[3]) : "r"(a));
}
__device__ __forceinline__ void mma_bf16(float* c, const uint32_t* a, const uint32_t* b) {
    asm volatile(
        "mma.sync.aligned.m16n8k16.row.col.f32.bf16.bf16.f32 "
        "{%0,%1,%2,%3}, {%4,%5,%6,%7}, {%8,%9}, {%0,%1,%2,%3};"
        : "+f"(c[0]), "+f"(c[1]), "+f"(c[2]), "+f"(c[3])
        : "r"(a[0]), "r"(a[1]), "r"(a[2]), "r"(a[3]), "r"(b[0]), "r"(b[1]));
}

// If EH != nullptr: fp16 epilogue into EH (edge GEMM). Else fp32 into C0..C3 + bias.
__global__ __launch_bounds__(NTHR) void gemm_split(
    const __nv_bfloat16* __restrict__ Ahi, const __nv_bfloat16* __restrict__ Alo,
    const __nv_bfloat16* __restrict__ Bhi, const __nv_bfloat16* __restrict__ Blo,
    const float* __restrict__ bias,
    float* __restrict__ C0, float* __restrict__ C1,
    float* __restrict__ C2, float* __restrict__ C3,
    __half* __restrict__ EH,
    int M, int K)
{
    extern __shared__ __nv_bfloat16 smem[];

    const int tid  = threadIdx.x;
    const int wid  = tid >> 5;
    const int lane = tid & 31;
    const int m0   = blockIdx.x * BM;
    const int nglob0 = blockIdx.y * BN;

    const int wm = (wid & 3) * 32;
    const int wn = (wid >> 2) * 32;
    const int gr  = lane >> 2;
    const int tig = lane & 3;

    const int r0  = tid >> 2;
    const int cg0 = (tid & 3) * 8;
    const int gmA = m0 + r0;
    const int aok = (gmA < M) ? 16 : 0;
    const size_t arow = (size_t)(aok ? gmA : 0) * KPAD;
    const size_t brow = (size_t)(nglob0 + r0) * KPAD;

    const int nk = K / BK;

    float acc[2][4][4];
#pragma unroll
    for (int i = 0; i < 2; i++)
#pragma unroll
        for (int j = 0; j < 4; j++)
#pragma unroll
            for (int r = 0; r < 4; r++) acc[i][j][r] = 0.f;

    uint32_t sbase = smem_u32(smem);

    auto load_stage = [&](int st, int kc) {
        uint32_t b = sbase + (uint32_t)(st * STAGE_ELEMS) * 2;
        uint32_t d = b + (uint32_t)(r0 * LDS_A + cg0) * 2;
        cpa16(d,                    Ahi + arow + kc + cg0, aok);
        cpa16(d + (uint32_t)TSZ*2,  Alo + arow + kc + cg0, aok);
        cpa16(d + (uint32_t)TSZ*4,  Bhi + brow + kc + cg0, 16);
        cpa16(d + (uint32_t)TSZ*6,  Blo + brow + kc + cg0, 16);
        CP_COMMIT();
    };

    const int aRow = lane & 15;
    const int aCol = (lane >> 4) * 8;
    const uint32_t aOff = (uint32_t)((wm + aRow) * LDS_A + aCol) * 2;
    const int bRow = wn + (lane & 7) + ((lane >> 4) << 3);
    const int bCol = ((lane >> 3) & 1) * 8;
    const uint32_t bOff = (uint32_t)(bRow * LDS_A + bCol) * 2;

    load_stage(0, 0);
    if (nk > 1) load_stage(1, BK);

    for (int ki = 0; ki < nk; ki++) {
        if (ki + 2 < nk) {
            load_stage((ki + 2) % NSTAGE, (ki + 2) * BK);
            CP_WAIT(2);
        } else if (ki + 1 < nk) {
            CP_WAIT(1);
        } else {
            CP_WAIT(0);
        }
        __syncthreads();

        uint32_t stb = sbase + (uint32_t)((ki % NSTAGE) * STAGE_ELEMS) * 2;
        uint32_t aHiB = stb, aLoB = stb + TSZ * 2;
        uint32_t bHiB = stb + TSZ * 4, bLoB = stb + TSZ * 6;

#pragma unroll
        for (int ks = 0; ks < BK; ks += 16) {
            uint32_t ah[2][4], al[2][4];
#pragma unroll
            for (int mt = 0; mt < 2; mt++) {
                uint32_t o = aOff + (uint32_t)(mt * 16 * LDS_A + ks) * 2;
                ldsm4(ah[mt], aHiB + o);
                ldsm4(al[mt], aLoB + o);
            }
            uint32_t bhf[8], blf[8];
#pragma unroll
            for (int p = 0; p < 2; p++) {
                uint32_t o = bOff + (uint32_t)(p * 16 * LDS_A + ks) * 2;
                ldsm4(bhf + 4 * p, bHiB + o);
                ldsm4(blf + 4 * p, bLoB + o);
            }
#pragma unroll
            for (int mt = 0; mt < 2; mt++)
#pragma unroll
                for (int nt = 0; nt < 4; nt++) {
                    mma_bf16(acc[mt][nt], ah[mt], bhf + nt * 2);
                    mma_bf16(acc[mt][nt], ah[mt], blf + nt * 2);
                    mma_bf16(acc[mt][nt], al[mt], bhf + nt * 2);
                }
        }
        __syncthreads();
    }

    // ---- epilogue ----
    if (EH == nullptr) {
        const int ob = blockIdx.y >> 1;
        float* C = (ob == 0) ? C0 : (ob == 1) ? C1 : (ob == 2) ? C2 : C3;
        const int n0l = (blockIdx.y & 1) * BN;
#pragma unroll
        for (int nt = 0; nt < 4; nt++) {
            int lc = wn + nt * 8 + tig * 2;
            float2 b2 = *(const float2*)(bias + nglob0 + lc);
            int gc = n0l + lc;
#pragma unroll
            for (int mt = 0; mt < 2; mt++) {
                int gm = m0 + wm + mt * 16 + gr;
                if (gm < M) {
                    float2 v0 = make_float2(acc[mt][nt][0] + b2.x, acc[mt][nt][1] + b2.y);
                    *(float2*)(C + (size_t)gm * NOUT + gc) = v0;
                }
                if (gm + 8 < M) {
                    float2 v1 = make_float2(acc[mt][nt][2] + b2.x, acc[mt][nt][3] + b2.y);
                    *(float2*)(C + (size_t)(gm + 8) * NOUT + gc) = v1;
                }
            }
        }
    } else {
#pragma unroll
        for (int nt = 0; nt < 4; nt++) {
            int gc = nglob0 + wn + nt * 8 + tig * 2;
#pragma unroll
            for (int mt = 0; mt < 2; mt++) {
                int gm = m0 + wm + mt * 16 + gr;
                if (gm < M) {
                    __half2 h0 = __floats2half2_rn(acc[mt][nt][0], acc[mt][nt][1]);
                    *(__half2*)(EH + (size_t)gm * NOUT + gc) = h0;
                }
                if (gm + 8 < M) {
                    __half2 h1 = __floats2half2_rn(acc[mt][nt][2], acc[mt][nt][3]);
                    *(__half2*)(EH + (size_t)(gm + 8) * NOUT + gc) = h1;
                }
            }
        }
    }
}

// ==================== conversion kernels ====================
__global__ void split_feat(const float* __restrict__ X,
                           __nv_bfloat16* __restrict__ hi, __nv_bfloat16* __restrict__ lo,
                           int M, int Kin)
{
    int idx = blockIdx.x * blockDim.x + threadIdx.x;
    if (idx >= M * KPAD) return;
    int k = idx & (KPAD - 1);
    float v = 0.f;
    if (k < Kin) v = X[(size_t)(idx >> 8) * Kin + k];
    __nv_bfloat16 h = __float2bfloat16(v);
    hi[idx] = h;
    lo[idx] = __float2bfloat16(v - __bfloat162float(h));
}

// edge features, ORIGINAL order (streaming); only k < KEDGE written (GEMM reads K=224)
__global__ void split_feat_edge(const float* __restrict__ ea,
                                __nv_bfloat16* __restrict__ hi, __nv_bfloat16* __restrict__ lo)
{
    int idx = blockIdx.x * blockDim.x + threadIdx.x;
    if (idx >= EE * KPAD) return;
    int k = idx & (KPAD - 1);
    if (k >= KEDGE) return;
    int i = idx >> 8;
    float v = (k < EDD) ? ea[(size_t)i * EDD + k] : 0.f;
    __nv_bfloat16 h = __float2bfloat16(v);
    hi[idx] = h;
    lo[idx] = __float2bfloat16(v - __bfloat162float(h));
}

__global__ void split_weight(const float* __restrict__ W,
                             __nv_bfloat16* __restrict__ hi, __nv_bfloat16* __restrict__ lo,
                             int Kin)
{
    int idx = blockIdx.x * blockDim.x + threadIdx.x;
    if (idx >= NOUT * KPAD) return;
    int n = idx & 255, k = idx >> 8;
    float v = (k < Kin) ? W[(size_t)k * NOUT + n] : 0.f;
    __nv_bfloat16 h = __float2bfloat16(v);
    hi[(size_t)n * KPAD + k] = h;
    lo[(size_t)n * KPAD + k] = __float2bfloat16(v - __bfloat162float(h));
}

__global__ void pack_bias(const float* __restrict__ bq, const float* __restrict__ bk,
                          const float* __restrict__ bv, const float* __restrict__ bs,
                          float* __restrict__ out)
{
    int i = blockIdx.x * blockDim.x + threadIdx.x;
    if (i >= 4 * NOUT) return;
    const float* src = (i < 256) ? bq : (i < 512) ? bk : (i < 768) ? bv : bs;
    out[i] = src[i & 255];
}

// ==================== edge sort-by-dst (once per call) ====================
__global__ void zero_cnt(int* __restrict__ cnt) {
    int i = blockIdx.x * blockDim.x + threadIdx.x;
    if (i < NN) cnt[i] = 0;
}
__global__ void hist_dst(const int* __restrict__ dst, int* __restrict__ cnt) {
    int i = blockIdx.x * blockDim.x + threadIdx.x;
    if (i < EE) atomicAdd(&cnt[dst[i]], 1);
}
__global__ __launch_bounds__(1024) void scan_cnt(const int* __restrict__ cnt,
                                                 int* __restrict__ off, int* __restrict__ pos)
{
    __shared__ int ssum[1024];
    const int tid = threadIdx.x;
    const int PER = (NN + 1023) / 1024;
    const int base = tid * PER;
    int s = 0;
    for (int j = 0; j < PER; j++) {
        int i = base + j;
        if (i < NN) s += cnt[i];
    }
    ssum[tid] = s;
    __syncthreads();
    for (int d = 1; d < 1024; d <<= 1) {
        int t = (tid >= d) ? ssum[tid - d] : 0;
        __syncthreads();
        ssum[tid] += t;
        __syncthreads();
    }
    int run = (tid > 0) ? ssum[tid - 1] : 0;
    for (int j = 0; j < PER; j++) {
        int i = base + j;
        if (i < NN) {
            off[i] = run;
            pos[i] = run;
            run += cnt[i];
        }
    }
    if (tid == 1023) off[NN] = run;
}
__global__ void scatter_edges(const int* __restrict__ dst, const int* __restrict__ src,
                              int* __restrict__ pos, int* __restrict__ order,
                              int* __restrict__ srcs)
{
    int i = blockIdx.x * blockDim.x + threadIdx.x;
    if (i >= EE) return;
    int p = atomicAdd(&pos[dst[i]], 1);
    order[p] = i;
    srcs[p] = src[i];
}

// ==================== fused per-dst attention (softmax + agg + skip + out) ====================
// one warp per dst node; e rows fp16 in original order via order[] indirection
__global__ __launch_bounds__(256) void edge_dst(
    const float* __restrict__ q, const float* __restrict__ k,
    const __half* __restrict__ eemb, const float* __restrict__ v,
    const int* __restrict__ srcs, const int* __restrict__ order,
    const int* __restrict__ off, const float* __restrict__ skip,
    float* __restrict__ outf,
    __nv_bfloat16* __restrict__ hi, __nv_bfloat16* __restrict__ lo,
    int mode)
{
    int w = (blockIdx.x * blockDim.x + threadIdx.x) >> 5;
    if (w >= NN) return;
    const int lane = threadIdx.x & 31;
    const int h = lane >> 3;
    const int part = lane & 7;
    const int co = h * CC + part * 8;

    const int start = off[w], end = off[w + 1];

    const float4* qp = (const float4*)(q + (size_t)w * DNODE + co);
    float4 q0 = qp[0], q1 = qp[1];

    float acc[8] = {0.f, 0.f, 0.f, 0.f, 0.f, 0.f, 0.f, 0.f};
    float den = 0.f;

    for (int i = start; i < end; i++) {
        int s = srcs[i];
        int e = order[i];
        const float4* kp = (const float4*)(k + (size_t)s * DNODE + co);
        float4 k0 = kp[0], k1 = kp[1];

        uint4 eu = *(const uint4*)(eemb + (size_t)e * DNODE + co);
        const __half2* hp = (const __half2*)&eu;
        float2 ea = __half22float2(hp[0]);
        float2 eb = __half22float2(hp[1]);
        float2 ec = __half22float2(hp[2]);
        float2 ed = __half22float2(hp[3]);
        float4 e0 = make_float4(ea.x, ea.y, eb.x, eb.y);
        float4 e1 = make_float4(ec.x, ec.y, ed.x, ed.y);

        float dot = q0.x * (k0.x + e0.x) + q0.y * (k0.y + e0.y)
                  + q0.z * (k0.z + e0.z) + q0.w * (k0.w + e0.w)
                  + q1.x * (k1.x + e1.x) + q1.y * (k1.y + e1.y)
                  + q1.z * (k1.z + e1.z) + q1.w * (k1.w + e1.w);
        dot += __shfl_xor_sync(0xffffffffu, dot, 1);
        dot += __shfl_xor_sync(0xffffffffu, dot, 2);
        dot += __shfl_xor_sync(0xffffffffu, dot, 4);

        float ex = __expf(dot * 0.125f);   // 1/sqrt(64); range-safe in fp32
        den += ex;

        const float4* vp = (const float4*)(v + (size_t)s * DNODE + co);
        float4 v0 = vp[0], v1 = vp[1];
        acc[0] += ex * (v0.x + e0.x); acc[1] += ex * (v0.y + e0.y);
        acc[2] += ex * (v0.z + e0.z); acc[3] += ex * (v0.w + e0.w);
        acc[4] += ex * (v1.x + e1.x); acc[5] += ex * (v1.y + e1.y);
        acc[6] += ex * (v1.z + e1.z); acc[7] += ex * (v1.w + e1.w);
    }

    float inv = 1.0f / (den + 1e-16f);
    const float4* sp = (const float4*)(skip + (size_t)w * DNODE + co);
    float4 s0 = sp[0], s1 = sp[1];
    float r[8];
    r[0] = acc[0] * inv + s0.x; r[1] = acc[1] * inv + s0.y;
    r[2] = acc[2] * inv + s0.z; r[3] = acc[3] * inv + s0.w;
    r[4] = acc[4] * inv + s1.x; r[5] = acc[5] * inv + s1.y;
    r[6] = acc[6] * inv + s1.z; r[7] = acc[7] * inv + s1.w;

    if (mode == 1) {
        ushort4 hv[2], lv[2];
#pragma unroll
        for (int g = 0; g < 2; g++) {
#pragma unroll
            for (int j = 0; j < 4; j++) {
                float x = fmaxf(r[g * 4 + j], 0.f);
                __nv_bfloat16 hb = __float2bfloat16(x);
                __nv_bfloat16 lb = __float2bfloat16(x - __bfloat162float(hb));
                ((unsigned short*)&hv[g])[j] = *(unsigned short*)&hb;
                ((unsigned short*)&lv[g])[j] = *(unsigned short*)&lb;
            }
        }
        size_t base = (size_t)w * KPAD + co;
        *(ushort4*)(hi + base)     = hv[0];
        *(ushort4*)(lo + base)     = lv[0];
        *(ushort4*)(hi + base + 4) = hv[1];
        *(ushort4*)(lo + base + 4) = lv[1];
    } else {
        float4* op = (float4*)(outf + (size_t)w * DNODE + co);
        op[0] = make_float4(r[0], r[1], r[2], r[3]);
        op[1] = make_float4(r[4], r[5], r[6], r[7]);
    }
}

// ==================== host side ====================
static void run_layer(const __nv_bfloat16* ahi, const __nv_bfloat16* alo,
                      const __nv_bfloat16* ehi, const __nv_bfloat16* elo,
                      const __nv_bfloat16* whi, const __nv_bfloat16* wlo, size_t wstride,
                      const float* bias_packed,
                      const int* srcs, const int* order, const int* off,
                      float* q, float* k, float* v, __half* eh, float* skip,
                      float* outf, __nv_bfloat16* out_hi, __nv_bfloat16* out_lo, int mode)
{
    dim3 gn((NN + BM - 1) / BM, 8);
    dim3 ge((EE + BM - 1) / BM, 2);
    gemm_split<<<gn, NTHR, GEMM_SMEM>>>(ahi, alo, whi, wlo, bias_packed,
                                        q, k, v, skip, nullptr, NN, KPAD);
    gemm_split<<<ge, NTHR, GEMM_SMEM>>>(ehi, elo, whi + 4 * wstride, wlo + 4 * wstride,
                                        nullptr, nullptr, nullptr, nullptr, nullptr,
                                        eh, EE, KEDGE);

    edge_dst<<<(NN * 32 + 255) / 256, 256>>>(q, k, eh, v, srcs, order, off, skip,
                                             outf, out_hi, out_lo, mode);
}

extern "C" void kernel_launch(void* const* d_in, const int* in_sizes, int n_in,
                              void* d_out, int out_size)
{
    const float* x   = (const float*)d_in[0];
    const int*   ei  = (const int*)  d_in[1];
    const float* ea  = (const float*)d_in[2];
    // per layer, weight buffer order: Wq, Wk, Wv, Ws, We
    const float* W1[5] = { (const float*)d_in[3],  (const float*)d_in[5],
                           (const float*)d_in[7],  (const float*)d_in[10],
                           (const float*)d_in[9] };
    const float* W2[5] = { (const float*)d_in[12], (const float*)d_in[14],
                           (const float*)d_in[16], (const float*)d_in[19],
                           (const float*)d_in[18] };
    const int Kin[5] = { DNODE, DNODE, DNODE, DNODE, EDD };

    const int* src = ei;
    const int* dst = ei + EE;
    float* out = (float*)d_out;

    float *q, *k, *v, *skip, *bias;
    __half* eh;
    int *cnt, *off, *pos, *order, *srcs;
    __nv_bfloat16 *ahi, *alo, *ehi, *elo, *whi, *wlo;
    cudaGetSymbolAddress((void**)&q,     g_q);
    cudaGetSymbolAddress((void**)&k,     g_k);
    cudaGetSymbolAddress((void**)&v,     g_v);
    cudaGetSymbolAddress((void**)&skip,  g_skip);
    cudaGetSymbolAddress((void**)&eh,    g_eh);
    cudaGetSymbolAddress((void**)&cnt,   g_cnt);
    cudaGetSymbolAddress((void**)&off,   g_off);
    cudaGetSymbolAddress((void**)&pos,   g_pos);
    cudaGetSymbolAddress((void**)&order, g_order);
    cudaGetSymbolAddress((void**)&srcs,  g_srcs);
    cudaGetSymbolAddress((void**)&ahi,   g_ahi);
    cudaGetSymbolAddress((void**)&alo,   g_alo);
    cudaGetSymbolAddress((void**)&ehi,   g_ehi);
    cudaGetSymbolAddress((void**)&elo,   g_elo);
    cudaGetSymbolAddress((void**)&whi,   g_whi);
    cudaGetSymbolAddress((void**)&wlo,   g_wlo);
    cudaGetSymbolAddress((void**)&bias,  g_bias);
    const size_t WS = (size_t)NOUT * KPAD;

    cudaFuncSetAttribute(gemm_split, cudaFuncAttributeMaxDynamicSharedMemorySize, GEMM_SMEM);

    // ---- edge sort by dst (once; shared by both layers) ----
    zero_cnt<<<(NN + 255) / 256, 256>>>(cnt);
    hist_dst<<<(EE + 255) / 256, 256>>>(dst, cnt);
    scan_cnt<<<1, 1024>>>(cnt, off, pos);
    scatter_edges<<<(EE + 255) / 256, 256>>>(dst, src, pos, order, srcs);

    // ---- conversions ----
    for (int i = 0; i < 5; i++) {
        split_weight<<<(NOUT * KPAD + 255) / 256, 256>>>(W1[i], whi + i * WS,       wlo + i * WS,       Kin[i]);
        split_weight<<<(NOUT * KPAD + 255) / 256, 256>>>(W2[i], whi + (5 + i) * WS, wlo + (5 + i) * WS, Kin[i]);
    }
    pack_bias<<<4, 256>>>((const float*)d_in[4],  (const float*)d_in[6],
                          (const float*)d_in[8],  (const float*)d_in[11], bias);
    pack_bias<<<4, 256>>>((const float*)d_in[13], (const float*)d_in[15],
                          (const float*)d_in[17], (const float*)d_in[20], bias + 4 * NOUT);

    split_feat_edge<<<((size_t)EE * KPAD + 255) / 256, 256>>>(ea, ehi, elo);
    split_feat<<<((size_t)NN * KPAD + 255) / 256, 256>>>(x, ahi, alo, NN, DNODE);

    // ---- layer 1: edge_dst writes relu+bf16-split of output (layer-2 input) ----
    run_layer(ahi, alo, ehi, elo, whi, wlo, WS, bias, srcs, order, off,
              q, k, v, eh, skip, nullptr, ahi, alo, 1);

    // ---- layer 2: edge_dst writes d_out ----
    run_layer(ahi, alo, ehi, elo, whi + 5 * WS, wlo + 5 * WS, WS, bias + 4 * NOUT,
              srcs, order, off, q, k, v, eh, skip, out, nullptr, nullptr, 0);
}